// round 8
// baseline (speedup 1.0000x reference)
#include <cuda_runtime.h>
#include <cstdint>

#define NU_MAX 50000
#define NI_MAX 50000
#define E_MAX  100000

// ---------------- device scratch (static; no allocations allowed) ----------
__device__ float g_v_u[NU_MAX * 512];     // V projection, user
__device__ float g_v_i[NI_MAX * 512];     // V projection, item
__device__ float g_aqk_u[NU_MAX * 16];    // per node: [0..7]=aq, [8..15]=ak
__device__ float g_aqk_i[NI_MAX * 16];
__device__ float g_A_u[16 * 256];         // effective attn proj: rows 0..7 q, 8..15 k
__device__ float g_A_i[16 * 256];
__device__ float g_beff_u[16];
__device__ float g_beff_i[16];
__device__ unsigned g_mkey[3 * NU_MAX * 8];   // per-etype ordered-uint segment max
__device__ float g_den[3 * NU_MAX * 8];
__device__ float g_deg[3 * NU_MAX];
__device__ float g_edge[3 * E_MAX * 8];       // score -> exp -> attn (in place)

struct EP {
    const int* src; const int* dst;
    const float* aqk_s; const float* aqk_d;
    const float* v_s; float* outp;
    int E; int pad;
};
struct EP3 { EP e[3]; };

// ---------------- helpers ----------------
__device__ __forceinline__ unsigned fkey(float f) {
    unsigned u = __float_as_uint(f);
    return (u & 0x80000000u) ? ~u : (u | 0x80000000u);
}
__device__ __forceinline__ float keyf(unsigned k) {
    unsigned u = (k & 0x80000000u) ? (k & 0x7fffffffu) : ~k;
    return __uint_as_float(u);
}
__device__ __forceinline__ uint32_t to_tf32(float f) {
    uint32_t r;
    asm("cvt.rna.tf32.f32 %0, %1;" : "=r"(r) : "f"(f));
    return r;
}
__device__ __forceinline__ void mma_tf32(float* c, uint32_t a0, uint32_t a1,
                                         uint32_t a2, uint32_t a3,
                                         uint32_t b0, uint32_t b1) {
    asm("mma.sync.aligned.m16n8k8.row.col.f32.tf32.tf32.f32 "
        "{%0,%1,%2,%3}, {%4,%5,%6,%7}, {%8,%9}, {%0,%1,%2,%3};"
        : "+f"(c[0]), "+f"(c[1]), "+f"(c[2]), "+f"(c[3])
        : "r"(a0), "r"(a1), "r"(a2), "r"(a3), "r"(b0), "r"(b1));
}

// ---------------- prep: fold wa into Wq/Wk -> effective [16,256] matrices ---
__global__ void prep_kernel(const float* __restrict__ Wq_u, const float* __restrict__ bq_u,
                            const float* __restrict__ Wk_u, const float* __restrict__ bk_u,
                            const float* __restrict__ Wq_i, const float* __restrict__ bq_i,
                            const float* __restrict__ Wk_i, const float* __restrict__ bk_i,
                            const float* __restrict__ wa_u, const float* __restrict__ wa_i) {
    int b = blockIdx.x;  // 0:Wq_u 1:Wk_u 2:Wq_i 3:Wk_i
    const float* W    = (b == 0) ? Wq_u : (b == 1) ? Wk_u : (b == 2) ? Wq_i : Wk_i;
    const float* bias = (b == 0) ? bq_u : (b == 1) ? bk_u : (b == 2) ? bq_i : bk_i;
    const float* wa   = (b < 2) ? wa_u : wa_i;
    float* A  = (b < 2) ? g_A_u : g_A_i;
    float* be = (b < 2) ? g_beff_u : g_beff_i;
    int rowoff = (b & 1) * 8;
    int k = threadIdx.x;
    __shared__ float was[64];
    if (k < 64) was[k] = wa[k];
    __syncthreads();
#pragma unroll
    for (int h = 0; h < 8; h++) {
        float s = 0.f;
        for (int d = 0; d < 64; d++) s += W[(h * 64 + d) * 256 + k] * was[d];
        A[(rowoff + h) * 256 + k] = s;
    }
    if (k < 8) {
        float s = 0.f;
        for (int d = 0; d < 64; d++) s += bias[k * 64 + d] * was[d];
        be[rowoff + k] = s;
    }
}

// ---------------- attn projections: aq/ak = x @ A^T + beff  (16 outs/node) --
__global__ void attnproj_kernel(const float* __restrict__ X, int isUser) {
    const float* A  = isUser ? g_A_u : g_A_i;
    const float* be = isUser ? g_beff_u : g_beff_i;
    float* outp     = isUser ? g_aqk_u : g_aqk_i;
    __shared__ float xs[256];
    int n = blockIdx.x;
    xs[threadIdx.x] = X[(size_t)n * 256 + threadIdx.x];
    __syncthreads();
    int w = threadIdx.x >> 5, l = threadIdx.x & 31;
#pragma unroll
    for (int r = 0; r < 2; r++) {
        int j = w + r * 8;
        float s = 0.f;
#pragma unroll
        for (int c = 0; c < 8; c++) {
            int k = l + 32 * c;
            s += xs[k] * A[j * 256 + k];
        }
#pragma unroll
        for (int off = 16; off; off >>= 1) s += __shfl_down_sync(0xffffffffu, s, off);
        if (l == 0) outp[n * 16 + j] = s + be[j];
    }
}

// ---------------- V GEMM via mma.sync tf32 ----------------------------------
// C[M,512] = X[M,256] @ W[512,256]^T + b.
// CTA tile 128(m) x 128(n), K staged 32 at a time, 8 warps in 2(m) x 4(n).
// Each warp: 64x32 via 4x4 m16n8k8 fragments.
__global__ void __launch_bounds__(256) gemm_mma_kernel(const float* __restrict__ X,
                                                       const float* __restrict__ W,
                                                       const float* __restrict__ bias,
                                                       int isUser, int M) {
    float* C = isUser ? g_v_u : g_v_i;
    __shared__ uint32_t As[128][36];
    __shared__ uint32_t Bs[128][36];
    __shared__ float s_bias[128];

    int tid = threadIdx.x, lane = tid & 31, warp = tid >> 5;
    int wm = (warp & 1) * 64;         // warp m offset in tile
    int wn = (warp >> 1) * 32;        // warp n offset in tile
    int n0 = blockIdx.x * 128;
    int m0 = blockIdx.y * 128;
    int lq = lane >> 2;               // 0..7
    int lr = lane & 3;                // 0..3
    int srow = warp * 16;             // staging row base for this warp

    if (tid < 128) s_bias[tid] = bias[n0 + tid];

    float acc[4][4][4];
#pragma unroll
    for (int mt = 0; mt < 4; mt++)
#pragma unroll
        for (int nt = 0; nt < 4; nt++)
#pragma unroll
            for (int i = 0; i < 4; i++) acc[mt][nt][i] = 0.f;

    for (int c = 0; c < 8; c++) {
        // stage A: warp covers rows srow..srow+15, lane = k column (coalesced 128B rows)
#pragma unroll
        for (int half = 0; half < 2; half++) {
            float ra[8];
#pragma unroll
            for (int r = 0; r < 8; r++) {
                int row = srow + half * 8 + r;
                int gr = m0 + row;
                if (gr >= M) gr = M - 1;
                ra[r] = X[(size_t)gr * 256 + c * 32 + lane];
            }
#pragma unroll
            for (int r = 0; r < 8; r++)
                As[srow + half * 8 + r][lane] = to_tf32(ra[r]);
        }
        // stage B: same mapping over W rows (n dimension)
#pragma unroll
        for (int half = 0; half < 2; half++) {
            float rb[8];
#pragma unroll
            for (int r = 0; r < 8; r++) {
                int row = srow + half * 8 + r;
                rb[r] = W[(size_t)(n0 + row) * 256 + c * 32 + lane];
            }
#pragma unroll
            for (int r = 0; r < 8; r++)
                Bs[srow + half * 8 + r][lane] = to_tf32(rb[r]);
        }
        __syncthreads();

#pragma unroll
        for (int kk = 0; kk < 4; kk++) {
            int k0 = kk * 8;
            uint32_t b[4][2];
#pragma unroll
            for (int nt = 0; nt < 4; nt++) {
                int n = wn + nt * 8 + lq;
                b[nt][0] = Bs[n][k0 + lr];
                b[nt][1] = Bs[n][k0 + lr + 4];
            }
#pragma unroll
            for (int mt = 0; mt < 4; mt++) {
                int r0 = wm + mt * 16 + lq;
                uint32_t a0 = As[r0][k0 + lr];
                uint32_t a1 = As[r0 + 8][k0 + lr];
                uint32_t a2 = As[r0][k0 + lr + 4];
                uint32_t a3 = As[r0 + 8][k0 + lr + 4];
#pragma unroll
                for (int nt = 0; nt < 4; nt++)
                    mma_tf32(acc[mt][nt], a0, a1, a2, a3, b[nt][0], b[nt][1]);
            }
        }
        __syncthreads();
    }

    // epilogue: c0,c1 -> (row, col), (row, col+1); c2,c3 -> row+8
#pragma unroll
    for (int mt = 0; mt < 4; mt++) {
        int row = m0 + wm + mt * 16 + lq;
#pragma unroll
        for (int nt = 0; nt < 4; nt++) {
            int cl = wn + nt * 8 + 2 * lr;    // col within 128-tile
            float bx = s_bias[cl], by = s_bias[cl + 1];
            if (row < M) {
                float2 o = make_float2(acc[mt][nt][0] + bx, acc[mt][nt][1] + by);
                *(float2*)(C + (size_t)row * 512 + n0 + cl) = o;
            }
            if (row + 8 < M) {
                float2 o = make_float2(acc[mt][nt][2] + bx, acc[mt][nt][3] + by);
                *(float2*)(C + (size_t)(row + 8) * 512 + n0 + cl) = o;
            }
        }
    }
}

// ---------------- edge phase (all 3 etypes per launch; grid.y = etype) ------
__global__ void score_all(EP3 P) {
    int et = blockIdx.y;
    EP p = P.e[et];
    int e = blockIdx.x * blockDim.x + threadIdx.x;
    if (e >= p.E) return;
    int s = p.src[e], d = p.dst[e];
    unsigned* mkey = g_mkey + (size_t)et * NU_MAX * 8;
    float* deg = g_deg + (size_t)et * NU_MAX;
    float* edge = g_edge + (size_t)et * E_MAX * 8;
    float4 ak0 = *(const float4*)(p.aqk_s + s * 16 + 8);
    float4 ak1 = *(const float4*)(p.aqk_s + s * 16 + 12);
    float4 aq0 = *(const float4*)(p.aqk_d + d * 16);
    float4 aq1 = *(const float4*)(p.aqk_d + d * 16 + 4);
    float sc[8];
    sc[0] = (ak0.x + aq0.x) * 0.125f; sc[1] = (ak0.y + aq0.y) * 0.125f;
    sc[2] = (ak0.z + aq0.z) * 0.125f; sc[3] = (ak0.w + aq0.w) * 0.125f;
    sc[4] = (ak1.x + aq1.x) * 0.125f; sc[5] = (ak1.y + aq1.y) * 0.125f;
    sc[6] = (ak1.z + aq1.z) * 0.125f; sc[7] = (ak1.w + aq1.w) * 0.125f;
    *(float4*)(edge + e * 8)     = make_float4(sc[0], sc[1], sc[2], sc[3]);
    *(float4*)(edge + e * 8 + 4) = make_float4(sc[4], sc[5], sc[6], sc[7]);
#pragma unroll
    for (int h = 0; h < 8; h++) atomicMax(&mkey[d * 8 + h], fkey(sc[h]));
    atomicAdd(&deg[d], 1.0f);
}

__global__ void exp_all(EP3 P) {
    int et = blockIdx.y;
    EP p = P.e[et];
    int e = blockIdx.x * blockDim.x + threadIdx.x;
    if (e >= p.E) return;
    int d = p.dst[e];
    const unsigned* mkey = g_mkey + (size_t)et * NU_MAX * 8;
    float* den = g_den + (size_t)et * NU_MAX * 8;
    float* edge = g_edge + (size_t)et * E_MAX * 8;
    float4 s0 = *(const float4*)(edge + e * 8);
    float4 s1 = *(const float4*)(edge + e * 8 + 4);
    float sc[8] = {s0.x, s0.y, s0.z, s0.w, s1.x, s1.y, s1.z, s1.w};
    float ex[8];
#pragma unroll
    for (int h = 0; h < 8; h++) {
        float m = keyf(mkey[d * 8 + h]);
        ex[h] = __expf(sc[h] - m);
        atomicAdd(&den[d * 8 + h], ex[h]);
    }
    *(float4*)(edge + e * 8)     = make_float4(ex[0], ex[1], ex[2], ex[3]);
    *(float4*)(edge + e * 8 + 4) = make_float4(ex[4], ex[5], ex[6], ex[7]);
}

__global__ void attn_all(EP3 P) {
    int et = blockIdx.y;
    EP p = P.e[et];
    int e = blockIdx.x * blockDim.x + threadIdx.x;
    if (e >= p.E) return;
    int d = p.dst[e];
    const float* den = g_den + (size_t)et * NU_MAX * 8;
    const float* deg = g_deg + (size_t)et * NU_MAX;
    float* edge = g_edge + (size_t)et * E_MAX * 8;
    float id = 1.0f / fmaxf(deg[d], 1.0f);
    float4 e0 = *(const float4*)(edge + e * 8);
    float4 e1 = *(const float4*)(edge + e * 8 + 4);
    float ex[8] = {e0.x, e0.y, e0.z, e0.w, e1.x, e1.y, e1.z, e1.w};
    float a[8];
#pragma unroll
    for (int h = 0; h < 8; h++) a[h] = ex[h] / den[d * 8 + h] * id;
    *(float4*)(edge + e * 8)     = make_float4(a[0], a[1], a[2], a[3]);
    *(float4*)(edge + e * 8 + 4) = make_float4(a[4], a[5], a[6], a[7]);
}

// message scatter: one thread per (edge, float4-quad); contiguous 2KB per edge
__global__ void msg_all(EP3 P) {
    int et = blockIdx.y;
    EP p = P.e[et];
    int idx = blockIdx.x * blockDim.x + threadIdx.x;
    if (idx >= p.E * 128) return;
    int e = idx >> 7, q = idx & 127;
    int h = q >> 4;
    const float* edge = g_edge + (size_t)et * E_MAX * 8;
    int s = p.src[e], d = p.dst[e];
    float a = edge[e * 8 + h];
    float4 vv = *(const float4*)(p.v_s + (size_t)s * 512 + q * 4);
    float x = vv.x * a, y = vv.y * a, z = vv.z * a, w = vv.w * a;
    float* pd = p.outp + (size_t)d * 512 + q * 4;
    asm volatile("red.global.add.v4.f32 [%0], {%1,%2,%3,%4};"
                 :: "l"(pd), "f"(x), "f"(y), "f"(z), "f"(w)
                 : "memory");
}

// ---------------- host ----------------
extern "C" void kernel_launch(void* const* d_in, const int* in_sizes, int n_in,
                              void* d_out, int out_size) {
    const float* x_u  = (const float*)d_in[0];
    const float* x_i  = (const float*)d_in[1];
    const float* Wq_u = (const float*)d_in[2];  const float* bq_u = (const float*)d_in[3];
    const float* Wk_u = (const float*)d_in[4];  const float* bk_u = (const float*)d_in[5];
    const float* Wv_u = (const float*)d_in[6];  const float* bv_u = (const float*)d_in[7];
    const float* Wq_i = (const float*)d_in[8];  const float* bq_i = (const float*)d_in[9];
    const float* Wk_i = (const float*)d_in[10]; const float* bk_i = (const float*)d_in[11];
    const float* Wv_i = (const float*)d_in[12]; const float* bv_i = (const float*)d_in[13];
    const float* wa_u = (const float*)d_in[14]; const float* wa_i = (const float*)d_in[15];
    const int* src_c  = (const int*)d_in[16];   const int* dst_c  = (const int*)d_in[17];
    const int* src_cb = (const int*)d_in[18];   const int* dst_cb = (const int*)d_in[19];
    const int* src_f  = (const int*)d_in[20];   const int* dst_f  = (const int*)d_in[21];

    int NU = in_sizes[0] / 256;
    int NI = in_sizes[1] / 256;
    int E0 = in_sizes[16], E1 = in_sizes[18], E2 = in_sizes[20];
    int Emax = E0 > E1 ? E0 : E1; if (E2 > Emax) Emax = E2;

    float* out_user = (float*)d_out;
    float* out_item = out_user + (size_t)NU * 512;

    void *p_mkey, *p_den, *p_deg, *p_vu, *p_vi;
    cudaGetSymbolAddress(&p_mkey, g_mkey);
    cudaGetSymbolAddress(&p_den, g_den);
    cudaGetSymbolAddress(&p_deg, g_deg);
    cudaGetSymbolAddress(&p_vu, g_v_u);
    cudaGetSymbolAddress(&p_vi, g_v_i);

    void *p_aqku, *p_aqki;
    cudaGetSymbolAddress(&p_aqku, g_aqk_u);
    cudaGetSymbolAddress(&p_aqki, g_aqk_i);

    cudaMemsetAsync(d_out, 0, (size_t)(NU + NI) * 512 * sizeof(float));
    cudaMemsetAsync(p_mkey, 0, sizeof(unsigned) * 3 * NU_MAX * 8);
    cudaMemsetAsync(p_den, 0, sizeof(float) * 3 * NU_MAX * 8);
    cudaMemsetAsync(p_deg, 0, sizeof(float) * 3 * NU_MAX);

    prep_kernel<<<4, 256>>>(Wq_u, bq_u, Wk_u, bk_u, Wq_i, bq_i, Wk_i, bk_i, wa_u, wa_i);
    attnproj_kernel<<<NU, 256>>>(x_u, 1);
    attnproj_kernel<<<NI, 256>>>(x_i, 0);
    gemm_mma_kernel<<<dim3(4, (NU + 127) / 128), 256>>>(x_u, Wv_u, bv_u, 1, NU);
    gemm_mma_kernel<<<dim3(4, (NI + 127) / 128), 256>>>(x_i, Wv_i, bv_i, 0, NI);

    EP3 P;
    // ('user','clicks','item'): src=user, dst=item -> h_item
    P.e[0] = {src_c, dst_c, (const float*)p_aqku, (const float*)p_aqki,
              (const float*)p_vu, out_item, E0, 0};
    // ('item','clicked_by','user'): src=item, dst=user -> h_user
    P.e[1] = {src_cb, dst_cb, (const float*)p_aqki, (const float*)p_aqku,
              (const float*)p_vi, out_user, E1, 0};
    // ('user','follows','user') -> h_user (accumulates via red.add)
    P.e[2] = {src_f, dst_f, (const float*)p_aqku, (const float*)p_aqku,
              (const float*)p_vu, out_user, E2, 0};

    dim3 gb((Emax + 255) / 256, 3);
    score_all<<<gb, 256>>>(P);
    exp_all<<<gb, 256>>>(P);
    attn_all<<<gb, 256>>>(P);
    msg_all<<<dim3((Emax * 128 + 255) / 256, 3), 256>>>(P);
}

// round 9
// speedup vs baseline: 1.3489x; 1.3489x over previous
#include <cuda_runtime.h>
#include <cstdint>

#define NU_MAX 50000
#define NI_MAX 50000
#define E_MAX  100000

// ---------------- device scratch (static; no allocations allowed) ----------
__device__ float g_v_u[NU_MAX * 512];     // V projection, user
__device__ float g_v_i[NI_MAX * 512];     // V projection, item
__device__ float g_aqk_u[NU_MAX * 16];    // per node: [0..7]=aq, [8..15]=ak
__device__ float g_aqk_i[NI_MAX * 16];
__device__ float g_A_u[16 * 256];         // effective attn proj: rows 0..7 q, 8..15 k
__device__ float g_A_i[16 * 256];
__device__ float g_beff_u[16];
__device__ float g_beff_i[16];
__device__ float g_den[3 * NU_MAX * 8];
__device__ float g_deg[3 * NU_MAX];
__device__ float g_edge[3 * E_MAX * 8];   // exp(score) -> attn (in place)

struct EP {
    const int* src; const int* dst;
    const float* aqk_s; const float* aqk_d;
    const float* v_s; float* outp;
    int E; int pad;
};
struct EP3 { EP e[3]; };

// ---------------- helpers ----------------
__device__ __forceinline__ uint32_t to_tf32(float f) {
    uint32_t r;
    asm("cvt.rna.tf32.f32 %0, %1;" : "=r"(r) : "f"(f));
    return r;
}
__device__ __forceinline__ void mma_tf32(float* c, uint32_t a0, uint32_t a1,
                                         uint32_t a2, uint32_t a3,
                                         uint32_t b0, uint32_t b1) {
    asm("mma.sync.aligned.m16n8k8.row.col.f32.tf32.tf32.f32 "
        "{%0,%1,%2,%3}, {%4,%5,%6,%7}, {%8,%9}, {%0,%1,%2,%3};"
        : "+f"(c[0]), "+f"(c[1]), "+f"(c[2]), "+f"(c[3])
        : "r"(a0), "r"(a1), "r"(a2), "r"(a3), "r"(b0), "r"(b1));
}

// ---------------- prep: fold wa into Wq/Wk -> effective [16,256] matrices ---
__global__ void prep_kernel(const float* __restrict__ Wq_u, const float* __restrict__ bq_u,
                            const float* __restrict__ Wk_u, const float* __restrict__ bk_u,
                            const float* __restrict__ Wq_i, const float* __restrict__ bq_i,
                            const float* __restrict__ Wk_i, const float* __restrict__ bk_i,
                            const float* __restrict__ wa_u, const float* __restrict__ wa_i) {
    int b = blockIdx.x;  // 0:Wq_u 1:Wk_u 2:Wq_i 3:Wk_i
    const float* W    = (b == 0) ? Wq_u : (b == 1) ? Wk_u : (b == 2) ? Wq_i : Wk_i;
    const float* bias = (b == 0) ? bq_u : (b == 1) ? bk_u : (b == 2) ? bq_i : bk_i;
    const float* wa   = (b < 2) ? wa_u : wa_i;
    float* A  = (b < 2) ? g_A_u : g_A_i;
    float* be = (b < 2) ? g_beff_u : g_beff_i;
    int rowoff = (b & 1) * 8;
    int k = threadIdx.x;
    __shared__ float was[64];
    if (k < 64) was[k] = wa[k];
    __syncthreads();
#pragma unroll
    for (int h = 0; h < 8; h++) {
        float s = 0.f;
        for (int d = 0; d < 64; d++) s += W[(h * 64 + d) * 256 + k] * was[d];
        A[(rowoff + h) * 256 + k] = s;
    }
    if (k < 8) {
        float s = 0.f;
        for (int d = 0; d < 64; d++) s += bias[k * 64 + d] * was[d];
        be[rowoff + k] = s;
    }
}

// ---------------- attn projections: aq/ak = x @ A^T + beff  (16 outs/node) --
__global__ void attnproj_kernel(const float* __restrict__ X, int isUser) {
    const float* A  = isUser ? g_A_u : g_A_i;
    const float* be = isUser ? g_beff_u : g_beff_i;
    float* outp     = isUser ? g_aqk_u : g_aqk_i;
    __shared__ float xs[256];
    int n = blockIdx.x;
    xs[threadIdx.x] = X[(size_t)n * 256 + threadIdx.x];
    __syncthreads();
    int w = threadIdx.x >> 5, l = threadIdx.x & 31;
#pragma unroll
    for (int r = 0; r < 2; r++) {
        int j = w + r * 8;
        float s = 0.f;
#pragma unroll
        for (int c = 0; c < 8; c++) {
            int k = l + 32 * c;
            s += xs[k] * A[j * 256 + k];
        }
#pragma unroll
        for (int off = 16; off; off >>= 1) s += __shfl_down_sync(0xffffffffu, s, off);
        if (l == 0) outp[n * 16 + j] = s + be[j];
    }
}

// ---------------- V GEMM via mma.sync tf32 (R4 config: known 153us) ---------
// C[M,512] = X[M,256] @ W[512,256]^T + b.
// CTA tile 128(m) x 64(n), K staged 32 at a time, 8 warps in 4(m) x 2(n).
// Each warp: 32x32 via 2x4 m16n8k8 fragments.
__global__ void __launch_bounds__(256) gemm_mma_kernel(const float* __restrict__ X,
                                                       const float* __restrict__ W,
                                                       const float* __restrict__ bias,
                                                       int isUser, int M) {
    float* C = isUser ? g_v_u : g_v_i;
    __shared__ uint32_t As[128][36];
    __shared__ uint32_t Bs[64][36];
    __shared__ float s_bias[64];

    int tid = threadIdx.x, lane = tid & 31, warp = tid >> 5;
    int wm = (warp & 3) * 32;         // warp m offset in tile
    int wn = (warp >> 2) * 32;        // warp n offset in tile
    int n0 = blockIdx.x * 64;
    int m0 = blockIdx.y * 128;
    int lq = lane >> 2;               // 0..7
    int lr = lane & 3;                // 0..3

    if (tid < 64) s_bias[tid] = bias[n0 + tid];

    float acc[2][4][4];
#pragma unroll
    for (int mt = 0; mt < 2; mt++)
#pragma unroll
        for (int nt = 0; nt < 4; nt++)
#pragma unroll
            for (int i = 0; i < 4; i++) acc[mt][nt][i] = 0.f;

    for (int c = 0; c < 8; c++) {
        // stage A: 128 rows x 32 cols
        {
            int row = tid >> 1, seg = (tid & 1) * 16;
            int gr = m0 + row;
            if (gr >= M) gr = M - 1;
            const float* p = X + (size_t)gr * 256 + c * 32 + seg;
#pragma unroll
            for (int q = 0; q < 4; q++) {
                float4 v = *(const float4*)(p + q * 4);
                As[row][seg + q * 4 + 0] = to_tf32(v.x);
                As[row][seg + q * 4 + 1] = to_tf32(v.y);
                As[row][seg + q * 4 + 2] = to_tf32(v.z);
                As[row][seg + q * 4 + 3] = to_tf32(v.w);
            }
        }
        // stage B: 64 rows (n) x 32 cols (k)
        {
            int row = tid >> 2, seg = (tid & 3) * 8;
            const float* p = W + (size_t)(n0 + row) * 256 + c * 32 + seg;
#pragma unroll
            for (int q = 0; q < 2; q++) {
                float4 v = *(const float4*)(p + q * 4);
                Bs[row][seg + q * 4 + 0] = to_tf32(v.x);
                Bs[row][seg + q * 4 + 1] = to_tf32(v.y);
                Bs[row][seg + q * 4 + 2] = to_tf32(v.z);
                Bs[row][seg + q * 4 + 3] = to_tf32(v.w);
            }
        }
        __syncthreads();

#pragma unroll
        for (int kk = 0; kk < 4; kk++) {
            int k0 = kk * 8;
            uint32_t b[4][2];
#pragma unroll
            for (int nt = 0; nt < 4; nt++) {
                int n = wn + nt * 8 + lq;
                b[nt][0] = Bs[n][k0 + lr];
                b[nt][1] = Bs[n][k0 + lr + 4];
            }
#pragma unroll
            for (int mt = 0; mt < 2; mt++) {
                int r0 = wm + mt * 16 + lq;
                uint32_t a0 = As[r0][k0 + lr];
                uint32_t a1 = As[r0 + 8][k0 + lr];
                uint32_t a2 = As[r0][k0 + lr + 4];
                uint32_t a3 = As[r0 + 8][k0 + lr + 4];
#pragma unroll
                for (int nt = 0; nt < 4; nt++)
                    mma_tf32(acc[mt][nt], a0, a1, a2, a3, b[nt][0], b[nt][1]);
            }
        }
        __syncthreads();
    }

    // epilogue: c0,c1 -> (row, col), (row, col+1); c2,c3 -> row+8
#pragma unroll
    for (int mt = 0; mt < 2; mt++) {
        int row = m0 + wm + mt * 16 + lq;
#pragma unroll
        for (int nt = 0; nt < 4; nt++) {
            int cl = wn + nt * 8 + 2 * lr;    // col within 64-tile
            float bx = s_bias[cl], by = s_bias[cl + 1];
            if (row < M) {
                float2 o = make_float2(acc[mt][nt][0] + bx, acc[mt][nt][1] + by);
                *(float2*)(C + (size_t)row * 512 + n0 + cl) = o;
            }
            if (row + 8 < M) {
                float2 o = make_float2(acc[mt][nt][2] + bx, acc[mt][nt][3] + by);
                *(float2*)(C + (size_t)(row + 8) * 512 + n0 + cl) = o;
            }
        }
    }
}

// ---------------- edge phase (all 3 etypes per launch; grid.y = etype) ------
// Scores are sums of small projections (|score| << 10), so softmax without
// max-subtraction is numerically safe and analytically identical:
// attn = exp(s)/sum(exp(s)) — the exp(max) factor cancels.
__global__ void score_all(EP3 P) {
    int et = blockIdx.y;
    EP p = P.e[et];
    int e = blockIdx.x * blockDim.x + threadIdx.x;
    if (e >= p.E) return;
    int s = p.src[e], d = p.dst[e];
    float* den = g_den + (size_t)et * NU_MAX * 8;
    float* deg = g_deg + (size_t)et * NU_MAX;
    float* edge = g_edge + (size_t)et * E_MAX * 8;
    float4 ak0 = *(const float4*)(p.aqk_s + s * 16 + 8);
    float4 ak1 = *(const float4*)(p.aqk_s + s * 16 + 12);
    float4 aq0 = *(const float4*)(p.aqk_d + d * 16);
    float4 aq1 = *(const float4*)(p.aqk_d + d * 16 + 4);
    float ex[8];
    ex[0] = __expf((ak0.x + aq0.x) * 0.125f);
    ex[1] = __expf((ak0.y + aq0.y) * 0.125f);
    ex[2] = __expf((ak0.z + aq0.z) * 0.125f);
    ex[3] = __expf((ak0.w + aq0.w) * 0.125f);
    ex[4] = __expf((ak1.x + aq1.x) * 0.125f);
    ex[5] = __expf((ak1.y + aq1.y) * 0.125f);
    ex[6] = __expf((ak1.z + aq1.z) * 0.125f);
    ex[7] = __expf((ak1.w + aq1.w) * 0.125f);
    *(float4*)(edge + e * 8)     = make_float4(ex[0], ex[1], ex[2], ex[3]);
    *(float4*)(edge + e * 8 + 4) = make_float4(ex[4], ex[5], ex[6], ex[7]);
#pragma unroll
    for (int h = 0; h < 8; h++) atomicAdd(&den[d * 8 + h], ex[h]);
    atomicAdd(&deg[d], 1.0f);
}

__global__ void attn_all(EP3 P) {
    int et = blockIdx.y;
    EP p = P.e[et];
    int e = blockIdx.x * blockDim.x + threadIdx.x;
    if (e >= p.E) return;
    int d = p.dst[e];
    const float* den = g_den + (size_t)et * NU_MAX * 8;
    const float* deg = g_deg + (size_t)et * NU_MAX;
    float* edge = g_edge + (size_t)et * E_MAX * 8;
    float id = 1.0f / fmaxf(deg[d], 1.0f);
    float4 e0 = *(const float4*)(edge + e * 8);
    float4 e1 = *(const float4*)(edge + e * 8 + 4);
    float ex[8] = {e0.x, e0.y, e0.z, e0.w, e1.x, e1.y, e1.z, e1.w};
    float a[8];
#pragma unroll
    for (int h = 0; h < 8; h++) a[h] = ex[h] / den[d * 8 + h] * id;
    *(float4*)(edge + e * 8)     = make_float4(a[0], a[1], a[2], a[3]);
    *(float4*)(edge + e * 8 + 4) = make_float4(a[4], a[5], a[6], a[7]);
}

// message scatter: one thread per (edge, float4-quad); contiguous 2KB per edge
__global__ void msg_all(EP3 P) {
    int et = blockIdx.y;
    EP p = P.e[et];
    int idx = blockIdx.x * blockDim.x + threadIdx.x;
    if (idx >= p.E * 128) return;
    int e = idx >> 7, q = idx & 127;
    int h = q >> 4;
    const float* edge = g_edge + (size_t)et * E_MAX * 8;
    int s = p.src[e], d = p.dst[e];
    float a = edge[e * 8 + h];
    float4 vv = *(const float4*)(p.v_s + (size_t)s * 512 + q * 4);
    float x = vv.x * a, y = vv.y * a, z = vv.z * a, w = vv.w * a;
    float* pd = p.outp + (size_t)d * 512 + q * 4;
    asm volatile("red.global.add.v4.f32 [%0], {%1,%2,%3,%4};"
                 :: "l"(pd), "f"(x), "f"(y), "f"(z), "f"(w)
                 : "memory");
}

// ---------------- host ----------------
extern "C" void kernel_launch(void* const* d_in, const int* in_sizes, int n_in,
                              void* d_out, int out_size) {
    const float* x_u  = (const float*)d_in[0];
    const float* x_i  = (const float*)d_in[1];
    const float* Wq_u = (const float*)d_in[2];  const float* bq_u = (const float*)d_in[3];
    const float* Wk_u = (const float*)d_in[4];  const float* bk_u = (const float*)d_in[5];
    const float* Wv_u = (const float*)d_in[6];  const float* bv_u = (const float*)d_in[7];
    const float* Wq_i = (const float*)d_in[8];  const float* bq_i = (const float*)d_in[9];
    const float* Wk_i = (const float*)d_in[10]; const float* bk_i = (const float*)d_in[11];
    const float* Wv_i = (const float*)d_in[12]; const float* bv_i = (const float*)d_in[13];
    const float* wa_u = (const float*)d_in[14]; const float* wa_i = (const float*)d_in[15];
    const int* src_c  = (const int*)d_in[16];   const int* dst_c  = (const int*)d_in[17];
    const int* src_cb = (const int*)d_in[18];   const int* dst_cb = (const int*)d_in[19];
    const int* src_f  = (const int*)d_in[20];   const int* dst_f  = (const int*)d_in[21];

    int NU = in_sizes[0] / 256;
    int NI = in_sizes[1] / 256;
    int E0 = in_sizes[16], E1 = in_sizes[18], E2 = in_sizes[20];
    int Emax = E0 > E1 ? E0 : E1; if (E2 > Emax) Emax = E2;

    float* out_user = (float*)d_out;
    float* out_item = out_user + (size_t)NU * 512;

    void *p_den, *p_deg, *p_vu, *p_vi, *p_aqku, *p_aqki;
    cudaGetSymbolAddress(&p_den, g_den);
    cudaGetSymbolAddress(&p_deg, g_deg);
    cudaGetSymbolAddress(&p_vu, g_v_u);
    cudaGetSymbolAddress(&p_vi, g_v_i);
    cudaGetSymbolAddress(&p_aqku, g_aqk_u);
    cudaGetSymbolAddress(&p_aqki, g_aqk_i);

    cudaMemsetAsync(d_out, 0, (size_t)(NU + NI) * 512 * sizeof(float));
    cudaMemsetAsync(p_den, 0, sizeof(float) * 3 * NU_MAX * 8);
    cudaMemsetAsync(p_deg, 0, sizeof(float) * 3 * NU_MAX);

    prep_kernel<<<4, 256>>>(Wq_u, bq_u, Wk_u, bk_u, Wq_i, bq_i, Wk_i, bk_i, wa_u, wa_i);
    attnproj_kernel<<<NU, 256>>>(x_u, 1);
    attnproj_kernel<<<NI, 256>>>(x_i, 0);
    gemm_mma_kernel<<<dim3(8, (NU + 127) / 128), 256>>>(x_u, Wv_u, bv_u, 1, NU);
    gemm_mma_kernel<<<dim3(8, (NI + 127) / 128), 256>>>(x_i, Wv_i, bv_i, 0, NI);

    EP3 P;
    // ('user','clicks','item'): src=user, dst=item -> h_item
    P.e[0] = {src_c, dst_c, (const float*)p_aqku, (const float*)p_aqki,
              (const float*)p_vu, out_item, E0, 0};
    // ('item','clicked_by','user'): src=item, dst=user -> h_user
    P.e[1] = {src_cb, dst_cb, (const float*)p_aqki, (const float*)p_aqku,
              (const float*)p_vi, out_user, E1, 0};
    // ('user','follows','user') -> h_user (accumulates via red.add)
    P.e[2] = {src_f, dst_f, (const float*)p_aqku, (const float*)p_aqku,
              (const float*)p_vu, out_user, E2, 0};

    dim3 gb((Emax + 255) / 256, 3);
    score_all<<<gb, 256>>>(P);
    attn_all<<<gb, 256>>>(P);
    msg_all<<<dim3((Emax * 128 + 255) / 256, 3), 256>>>(P);
}

// round 11
// speedup vs baseline: 1.4021x; 1.0394x over previous
#include <cuda_runtime.h>
#include <cstdint>

#define NU_MAX 50000
#define NI_MAX 50000
#define E_MAX  100000

// ---------------- device scratch (static; no allocations allowed) ----------
__device__ float g_v_u[NU_MAX * 512];     // V projection, user
__device__ float g_v_i[NI_MAX * 512];     // V projection, item
__device__ float g_aqk_u[NU_MAX * 16];    // per node: [0..7]=aq, [8..15]=ak
__device__ float g_aqk_i[NI_MAX * 16];
__device__ uint32_t g_xc_u[NU_MAX * 256]; // tf32(RNA)-converted X, user
__device__ uint32_t g_xc_i[NI_MAX * 256]; // tf32(RNA)-converted X, item
__device__ uint32_t g_wc_u[512 * 256];    // tf32(RNA)-converted Wv_user
__device__ uint32_t g_wc_i[512 * 256];    // tf32(RNA)-converted Wv_item
__device__ float g_A_u[16 * 256];         // effective attn proj: rows 0..7 q, 8..15 k
__device__ float g_A_i[16 * 256];
__device__ float g_beff_u[16];
__device__ float g_beff_i[16];
__device__ float g_den[3 * NU_MAX * 8];   // sum(exp) -> 1/(sum*deg) after norm_all
__device__ float g_deg[3 * NU_MAX];
__device__ float g_edge[3 * E_MAX * 8];   // exp(score)

struct EP {
    const int* src; const int* dst;
    const float* aqk_s; const float* aqk_d;
    const float* v_s; float* outp;
    int E; int pad;
};
struct EP3 { EP e[3]; };

// ---------------- helpers ----------------
__device__ __forceinline__ uint32_t to_tf32(float f) {
    uint32_t r;
    asm("cvt.rna.tf32.f32 %0, %1;" : "=r"(r) : "f"(f));
    return r;
}
__device__ __forceinline__ void mma_tf32(float* c, uint32_t a0, uint32_t a1,
                                         uint32_t a2, uint32_t a3,
                                         uint32_t b0, uint32_t b1) {
    asm("mma.sync.aligned.m16n8k8.row.col.f32.tf32.tf32.f32 "
        "{%0,%1,%2,%3}, {%4,%5,%6,%7}, {%8,%9}, {%0,%1,%2,%3};"
        : "+f"(c[0]), "+f"(c[1]), "+f"(c[2]), "+f"(c[3])
        : "r"(a0), "r"(a1), "r"(a2), "r"(a3), "r"(b0), "r"(b1));
}
__device__ __forceinline__ void cp16(uint32_t smem_dst, const void* gsrc) {
    asm volatile("cp.async.cg.shared.global [%0], [%1], 16;"
                 :: "r"(smem_dst), "l"(gsrc) : "memory");
}

// ---------------- prep: fold wa into Wq/Wk -> effective [16,256] matrices ---
__global__ void prep_kernel(const float* __restrict__ Wq_u, const float* __restrict__ bq_u,
                            const float* __restrict__ Wk_u, const float* __restrict__ bk_u,
                            const float* __restrict__ Wq_i, const float* __restrict__ bq_i,
                            const float* __restrict__ Wk_i, const float* __restrict__ bk_i,
                            const float* __restrict__ wa_u, const float* __restrict__ wa_i) {
    int b = blockIdx.x;  // 0:Wq_u 1:Wk_u 2:Wq_i 3:Wk_i
    const float* W    = (b == 0) ? Wq_u : (b == 1) ? Wk_u : (b == 2) ? Wq_i : Wk_i;
    const float* bias = (b == 0) ? bq_u : (b == 1) ? bk_u : (b == 2) ? bq_i : bk_i;
    const float* wa   = (b < 2) ? wa_u : wa_i;
    float* A  = (b < 2) ? g_A_u : g_A_i;
    float* be = (b < 2) ? g_beff_u : g_beff_i;
    int rowoff = (b & 1) * 8;
    int k = threadIdx.x;
    __shared__ float was[64];
    if (k < 64) was[k] = wa[k];
    __syncthreads();
#pragma unroll
    for (int h = 0; h < 8; h++) {
        float s = 0.f;
        for (int d = 0; d < 64; d++) s += W[(h * 64 + d) * 256 + k] * was[d];
        A[(rowoff + h) * 256 + k] = s;
    }
    if (k < 8) {
        float s = 0.f;
        for (int d = 0; d < 64; d++) s += bias[k * 64 + d] * was[d];
        be[rowoff + k] = s;
    }
}

// ---------------- Wv -> tf32 conversion (RNA, same numerics as before) ------
__global__ void wconv_kernel(const float* __restrict__ Wv_u,
                             const float* __restrict__ Wv_i) {
    int i = blockIdx.x * blockDim.x + threadIdx.x;  // 512*256 total
    g_wc_u[i] = to_tf32(Wv_u[i]);
    g_wc_i[i] = to_tf32(Wv_i[i]);
}

// ---------------- attn projections + X -> tf32 copy -------------------------
__global__ void attnproj_kernel(const float* __restrict__ X, int isUser) {
    const float* A  = isUser ? g_A_u : g_A_i;
    const float* be = isUser ? g_beff_u : g_beff_i;
    float* outp     = isUser ? g_aqk_u : g_aqk_i;
    uint32_t* xc    = isUser ? g_xc_u : g_xc_i;
    __shared__ float xs[256];
    int n = blockIdx.x;
    float xv = X[(size_t)n * 256 + threadIdx.x];
    xs[threadIdx.x] = xv;
    xc[(size_t)n * 256 + threadIdx.x] = to_tf32(xv);
    __syncthreads();
    int w = threadIdx.x >> 5, l = threadIdx.x & 31;
#pragma unroll
    for (int r = 0; r < 2; r++) {
        int j = w + r * 8;
        float s = 0.f;
#pragma unroll
        for (int c = 0; c < 8; c++) {
            int k = l + 32 * c;
            s += xs[k] * A[j * 256 + k];
        }
#pragma unroll
        for (int off = 16; off; off >>= 1) s += __shfl_down_sync(0xffffffffu, s, off);
        if (l == 0) outp[n * 16 + j] = s + be[j];
    }
}

// ---------------- V GEMM: cp.async double-buffered mma.sync tf32 ------------
// C[M,512] = Xc[M,256] @ Wc[512,256]^T + b (operands pre-converted to tf32).
// CTA tile 128(m) x 64(n), K staged 32 at a time, 2-stage cp.async pipeline.
// 8 warps in 4(m) x 2(n); each warp 32x32 via 2x4 m16n8k8 fragments.
__global__ void __launch_bounds__(256) gemm_cp_kernel(const uint32_t* __restrict__ Xc,
                                                      const uint32_t* __restrict__ Wc,
                                                      const float* __restrict__ bias,
                                                      int isUser, int M) {
    float* C = isUser ? g_v_u : g_v_i;
    __shared__ uint32_t As[2][128][36];
    __shared__ uint32_t Bs[2][64][36];
    __shared__ float s_bias[64];

    int tid = threadIdx.x, lane = tid & 31, warp = tid >> 5;
    int wm = (warp & 3) * 32;
    int wn = (warp >> 2) * 32;
    int n0 = blockIdx.x * 64;
    int m0 = blockIdx.y * 128;
    int lq = lane >> 2;
    int lr = lane & 3;

    if (tid < 64) s_bias[tid] = bias[n0 + tid];

    // cp.async mappings: A: 128 rows x 8 chunks(16B); thread -> (row, 4 chunks)
    int arow = tid >> 1, acol = (tid & 1) * 16;          // col in floats (0 or 16)
    int gr = m0 + arow; if (gr >= M) gr = M - 1;
    const uint32_t* a_src = Xc + (size_t)gr * 256 + acol;
    uint32_t a_dst[2];
    a_dst[0] = (uint32_t)__cvta_generic_to_shared(&As[0][arow][acol]);
    a_dst[1] = (uint32_t)__cvta_generic_to_shared(&As[1][arow][acol]);
    // B: 64 rows x 8 chunks; thread -> (row, 2 chunks)
    int brow = tid >> 2, bcol = (tid & 3) * 8;
    const uint32_t* b_src = Wc + (size_t)(n0 + brow) * 256 + bcol;
    uint32_t b_dst[2];
    b_dst[0] = (uint32_t)__cvta_generic_to_shared(&Bs[0][brow][bcol]);
    b_dst[1] = (uint32_t)__cvta_generic_to_shared(&Bs[1][brow][bcol]);

    float acc[2][4][4];
#pragma unroll
    for (int mt = 0; mt < 2; mt++)
#pragma unroll
        for (int nt = 0; nt < 4; nt++)
#pragma unroll
            for (int i = 0; i < 4; i++) acc[mt][nt][i] = 0.f;

#define ISSUE(c, buf) do { \
        const uint32_t* _as = a_src + (c) * 32; \
        const uint32_t* _bs = b_src + (c) * 32; \
        cp16(a_dst[buf] + 0,  _as + 0); \
        cp16(a_dst[buf] + 16, _as + 4); \
        cp16(a_dst[buf] + 32, _as + 8); \
        cp16(a_dst[buf] + 48, _as + 12); \
        cp16(b_dst[buf] + 0,  _bs + 0); \
        cp16(b_dst[buf] + 16, _bs + 4); \
        asm volatile("cp.async.commit_group;" ::: "memory"); \
    } while (0)

    ISSUE(0, 0);
    ISSUE(1, 1);

#pragma unroll
    for (int c = 0; c < 8; c++) {
        if (c < 7) asm volatile("cp.async.wait_group 1;" ::: "memory");
        else       asm volatile("cp.async.wait_group 0;" ::: "memory");
        __syncthreads();
        int bf = c & 1;
#pragma unroll
        for (int kk = 0; kk < 4; kk++) {
            int k0 = kk * 8;
            uint32_t b[4][2];
#pragma unroll
            for (int nt = 0; nt < 4; nt++) {
                int n = wn + nt * 8 + lq;
                b[nt][0] = Bs[bf][n][k0 + lr];
                b[nt][1] = Bs[bf][n][k0 + lr + 4];
            }
#pragma unroll
            for (int mt = 0; mt < 2; mt++) {
                int r0 = wm + mt * 16 + lq;
                uint32_t a0 = As[bf][r0][k0 + lr];
                uint32_t a1 = As[bf][r0 + 8][k0 + lr];
                uint32_t a2 = As[bf][r0][k0 + lr + 4];
                uint32_t a3 = As[bf][r0 + 8][k0 + lr + 4];
#pragma unroll
                for (int nt = 0; nt < 4; nt++)
                    mma_tf32(acc[mt][nt], a0, a1, a2, a3, b[nt][0], b[nt][1]);
            }
        }
        __syncthreads();
        if (c + 2 < 8) ISSUE(c + 2, bf);
    }
#undef ISSUE

    // epilogue: c0,c1 -> (row, col), (row, col+1); c2,c3 -> row+8
#pragma unroll
    for (int mt = 0; mt < 2; mt++) {
        int row = m0 + wm + mt * 16 + lq;
#pragma unroll
        for (int nt = 0; nt < 4; nt++) {
            int cl = wn + nt * 8 + 2 * lr;
            float bx = s_bias[cl], by = s_bias[cl + 1];
            if (row < M) {
                float2 o = make_float2(acc[mt][nt][0] + bx, acc[mt][nt][1] + by);
                *(float2*)(C + (size_t)row * 512 + n0 + cl) = o;
            }
            if (row + 8 < M) {
                float2 o = make_float2(acc[mt][nt][2] + bx, acc[mt][nt][3] + by);
                *(float2*)(C + (size_t)(row + 8) * 512 + n0 + cl) = o;
            }
        }
    }
}

// ---------------- edge phase (all 3 etypes per launch; grid.y = etype) ------
// Scores are sums of small projections, so softmax without max-subtraction is
// numerically safe and analytically identical (exp(max) cancels).
__global__ void score_all(EP3 P) {
    int et = blockIdx.y;
    EP p = P.e[et];
    int e = blockIdx.x * blockDim.x + threadIdx.x;
    if (e >= p.E) return;
    int s = p.src[e], d = p.dst[e];
    float* den = g_den + (size_t)et * NU_MAX * 8;
    float* deg = g_deg + (size_t)et * NU_MAX;
    float* edge = g_edge + (size_t)et * E_MAX * 8;
    float4 ak0 = *(const float4*)(p.aqk_s + s * 16 + 8);
    float4 ak1 = *(const float4*)(p.aqk_s + s * 16 + 12);
    float4 aq0 = *(const float4*)(p.aqk_d + d * 16);
    float4 aq1 = *(const float4*)(p.aqk_d + d * 16 + 4);
    float ex[8];
    ex[0] = __expf((ak0.x + aq0.x) * 0.125f);
    ex[1] = __expf((ak0.y + aq0.y) * 0.125f);
    ex[2] = __expf((ak0.z + aq0.z) * 0.125f);
    ex[3] = __expf((ak0.w + aq0.w) * 0.125f);
    ex[4] = __expf((ak1.x + aq1.x) * 0.125f);
    ex[5] = __expf((ak1.y + aq1.y) * 0.125f);
    ex[6] = __expf((ak1.z + aq1.z) * 0.125f);
    ex[7] = __expf((ak1.w + aq1.w) * 0.125f);
    *(float4*)(edge + e * 8)     = make_float4(ex[0], ex[1], ex[2], ex[3]);
    *(float4*)(edge + e * 8 + 4) = make_float4(ex[4], ex[5], ex[6], ex[7]);
#pragma unroll
    for (int h = 0; h < 8; h++) atomicAdd(&den[d * 8 + h], ex[h]);
    atomicAdd(&deg[d], 1.0f);
}

// den[d,h] <- 1 / (den[d,h] * max(deg[d],1))  (per-node normalizer, in place)
__global__ void norm_all(int NUr, int NIr) {
    int et = blockIdx.y;
    int i = blockIdx.x * blockDim.x + threadIdx.x;
    int Nd = (et == 0) ? NIr : NUr;
    if (i >= Nd * 8) return;
    float* den = g_den + (size_t)et * NU_MAX * 8;
    const float* deg = g_deg + (size_t)et * NU_MAX;
    float dc = fmaxf(deg[i >> 3], 1.0f);
    den[i] = 1.0f / (den[i] * dc);
}

// message scatter: one thread per (edge, float4-quad); contiguous 2KB per edge
__global__ void msg_all(EP3 P) {
    int et = blockIdx.y;
    EP p = P.e[et];
    int idx = blockIdx.x * blockDim.x + threadIdx.x;
    if (idx >= p.E * 128) return;
    int e = idx >> 7, q = idx & 127;
    int h = q >> 4;
    const float* edge = g_edge + (size_t)et * E_MAX * 8;
    const float* den = g_den + (size_t)et * NU_MAX * 8;
    int s = p.src[e], d = p.dst[e];
    float a = edge[e * 8 + h] * __ldg(&den[d * 8 + h]);
    float4 vv = *(const float4*)(p.v_s + (size_t)s * 512 + q * 4);
    float x = vv.x * a, y = vv.y * a, z = vv.z * a, w = vv.w * a;
    float* pd = p.outp + (size_t)d * 512 + q * 4;
    asm volatile("red.global.add.v4.f32 [%0], {%1,%2,%3,%4};"
                 :: "l"(pd), "f"(x), "f"(y), "f"(z), "f"(w)
                 : "memory");
}

// ---------------- host ----------------
extern "C" void kernel_launch(void* const* d_in, const int* in_sizes, int n_in,
                              void* d_out, int out_size) {
    const float* x_u  = (const float*)d_in[0];
    const float* x_i  = (const float*)d_in[1];
    const float* Wq_u = (const float*)d_in[2];  const float* bq_u = (const float*)d_in[3];
    const float* Wk_u = (const float*)d_in[4];  const float* bk_u = (const float*)d_in[5];
    const float* Wv_u = (const float*)d_in[6];  const float* bv_u = (const float*)d_in[7];
    const float* Wq_i = (const float*)d_in[8];  const float* bq_i = (const float*)d_in[9];
    const float* Wk_i = (const float*)d_in[10]; const float* bk_i = (const float*)d_in[11];
    const float* Wv_i = (const float*)d_in[12]; const float* bv_i = (const float*)d_in[13];
    const float* wa_u = (const float*)d_in[14]; const float* wa_i = (const float*)d_in[15];
    const int* src_c  = (const int*)d_in[16];   const int* dst_c  = (const int*)d_in[17];
    const int* src_cb = (const int*)d_in[18];   const int* dst_cb = (const int*)d_in[19];
    const int* src_f  = (const int*)d_in[20];   const int* dst_f  = (const int*)d_in[21];

    int NU = in_sizes[0] / 256;
    int NI = in_sizes[1] / 256;
    int E0 = in_sizes[16], E1 = in_sizes[18], E2 = in_sizes[20];
    int Emax = E0 > E1 ? E0 : E1; if (E2 > Emax) Emax = E2;
    int Nmax = NU > NI ? NU : NI;

    float* out_user = (float*)d_out;
    float* out_item = out_user + (size_t)NU * 512;

    void *p_den, *p_deg, *p_vu, *p_vi, *p_aqku, *p_aqki, *p_xcu, *p_xci, *p_wcu, *p_wci;
    cudaGetSymbolAddress(&p_den, g_den);
    cudaGetSymbolAddress(&p_deg, g_deg);
    cudaGetSymbolAddress(&p_vu, g_v_u);
    cudaGetSymbolAddress(&p_vi, g_v_i);
    cudaGetSymbolAddress(&p_aqku, g_aqk_u);
    cudaGetSymbolAddress(&p_aqki, g_aqk_i);
    cudaGetSymbolAddress(&p_xcu, g_xc_u);
    cudaGetSymbolAddress(&p_xci, g_xc_i);
    cudaGetSymbolAddress(&p_wcu, g_wc_u);
    cudaGetSymbolAddress(&p_wci, g_wc_i);

    cudaMemsetAsync(d_out, 0, (size_t)(NU + NI) * 512 * sizeof(float));
    cudaMemsetAsync(p_den, 0, sizeof(float) * 3 * NU_MAX * 8);
    cudaMemsetAsync(p_deg, 0, sizeof(float) * 3 * NU_MAX);

    prep_kernel<<<4, 256>>>(Wq_u, bq_u, Wk_u, bk_u, Wq_i, bq_i, Wk_i, bk_i, wa_u, wa_i);
    wconv_kernel<<<512, 256>>>(Wv_u, Wv_i);
    attnproj_kernel<<<NU, 256>>>(x_u, 1);
    attnproj_kernel<<<NI, 256>>>(x_i, 0);
    gemm_cp_kernel<<<dim3(8, (NU + 127) / 128), 256>>>(
        (const uint32_t*)p_xcu, (const uint32_t*)p_wcu, bv_u, 1, NU);
    gemm_cp_kernel<<<dim3(8, (NI + 127) / 128), 256>>>(
        (const uint32_t*)p_xci, (const uint32_t*)p_wci, bv_i, 0, NI);

    EP3 P;
    // ('user','clicks','item'): src=user, dst=item -> h_item
    P.e[0] = {src_c, dst_c, (const float*)p_aqku, (const float*)p_aqki,
              (const float*)p_vu, out_item, E0, 0};
    // ('item','clicked_by','user'): src=item, dst=user -> h_user
    P.e[1] = {src_cb, dst_cb, (const float*)p_aqki, (const float*)p_aqku,
              (const float*)p_vi, out_user, E1, 0};
    // ('user','follows','user') -> h_user (accumulates via red.add)
    P.e[2] = {src_f, dst_f, (const float*)p_aqku, (const float*)p_aqku,
              (const float*)p_vu, out_user, E2, 0};

    dim3 gb((Emax + 255) / 256, 3);
    score_all<<<gb, 256>>>(P);
    norm_all<<<dim3((Nmax * 8 + 255) / 256, 3), 256>>>(NU, NI);
    msg_all<<<dim3((Emax * 128 + 255) / 256, 3), 256>>>(P);
}

// round 12
// speedup vs baseline: 1.5113x; 1.0779x over previous
#include <cuda_runtime.h>
#include <cstdint>

#define NU_MAX 50000
#define NI_MAX 50000
#define E_MAX  100000

// ---------------- device scratch (static; no allocations allowed) ----------
__device__ float g_v_u[NU_MAX * 512];     // V projection, user
__device__ float g_v_i[NI_MAX * 512];     // V projection, item
__device__ float g_aqk_u[NU_MAX * 16];    // per node: [0..7]=aq, [8..15]=ak
__device__ float g_aqk_i[NI_MAX * 16];
__device__ uint32_t g_xc_u[NU_MAX * 256]; // tf32(RNA)-converted X, user
__device__ uint32_t g_xc_i[NI_MAX * 256]; // tf32(RNA)-converted X, item
__device__ uint32_t g_wc_u[512 * 256];    // tf32(RNA)-converted Wv_user
__device__ uint32_t g_wc_i[512 * 256];    // tf32(RNA)-converted Wv_item
__device__ float g_A_u[16 * 256];         // effective attn proj: rows 0..7 q, 8..15 k
__device__ float g_A_i[16 * 256];
__device__ float g_beff_u[16];
__device__ float g_beff_i[16];
__device__ float g_den[3 * NU_MAX * 8];   // sum(exp) -> 1/(sum*deg) after norm_all
__device__ float g_deg[3 * NU_MAX];
__device__ float g_edge[3 * E_MAX * 8];   // exp(score)

struct EP {
    const int* src; const int* dst;
    const float* aqk_s; const float* aqk_d;
    const float* v_s; float* outp;
    int E; int pad;
};
struct EP3 { EP e[3]; };

// ---------------- helpers ----------------
__device__ __forceinline__ uint32_t to_tf32(float f) {
    uint32_t r;
    asm("cvt.rna.tf32.f32 %0, %1;" : "=r"(r) : "f"(f));
    return r;
}
__device__ __forceinline__ void mma_tf32(float* c, uint32_t a0, uint32_t a1,
                                         uint32_t a2, uint32_t a3,
                                         uint32_t b0, uint32_t b1) {
    asm("mma.sync.aligned.m16n8k8.row.col.f32.tf32.tf32.f32 "
        "{%0,%1,%2,%3}, {%4,%5,%6,%7}, {%8,%9}, {%0,%1,%2,%3};"
        : "+f"(c[0]), "+f"(c[1]), "+f"(c[2]), "+f"(c[3])
        : "r"(a0), "r"(a1), "r"(a2), "r"(a3), "r"(b0), "r"(b1));
}
__device__ __forceinline__ void cp16(uint32_t smem_dst, const void* gsrc) {
    asm volatile("cp.async.cg.shared.global [%0], [%1], 16;"
                 :: "r"(smem_dst), "l"(gsrc) : "memory");
}

// ---------------- prep: fold wa into Wq/Wk -> effective [16,256] matrices ---
__global__ void prep_kernel(const float* __restrict__ Wq_u, const float* __restrict__ bq_u,
                            const float* __restrict__ Wk_u, const float* __restrict__ bk_u,
                            const float* __restrict__ Wq_i, const float* __restrict__ bq_i,
                            const float* __restrict__ Wk_i, const float* __restrict__ bk_i,
                            const float* __restrict__ wa_u, const float* __restrict__ wa_i) {
    int b = blockIdx.x;  // 0:Wq_u 1:Wk_u 2:Wq_i 3:Wk_i
    const float* W    = (b == 0) ? Wq_u : (b == 1) ? Wk_u : (b == 2) ? Wq_i : Wk_i;
    const float* bias = (b == 0) ? bq_u : (b == 1) ? bk_u : (b == 2) ? bq_i : bk_i;
    const float* wa   = (b < 2) ? wa_u : wa_i;
    float* A  = (b < 2) ? g_A_u : g_A_i;
    float* be = (b < 2) ? g_beff_u : g_beff_i;
    int rowoff = (b & 1) * 8;
    int k = threadIdx.x;
    __shared__ float was[64];
    if (k < 64) was[k] = wa[k];
    __syncthreads();
#pragma unroll
    for (int h = 0; h < 8; h++) {
        float s = 0.f;
        for (int d = 0; d < 64; d++) s += W[(h * 64 + d) * 256 + k] * was[d];
        A[(rowoff + h) * 256 + k] = s;
    }
    if (k < 8) {
        float s = 0.f;
        for (int d = 0; d < 64; d++) s += bias[k * 64 + d] * was[d];
        be[rowoff + k] = s;
    }
}

// ---------------- Wv -> tf32 conversion (RNA, same numerics as before) ------
__global__ void wconv_kernel(const float* __restrict__ Wv_u,
                             const float* __restrict__ Wv_i) {
    int i = blockIdx.x * blockDim.x + threadIdx.x;  // 512*256 total
    g_wc_u[i] = to_tf32(Wv_u[i]);
    g_wc_i[i] = to_tf32(Wv_i[i]);
}

// ---------------- attn projections + X -> tf32 copy -------------------------
// Block = 16 nodes; thread (n = tid>>4, j = tid&15) computes aqk[n][j] with a
// float4 accumulator (4 independent FMA chains). No shuffles.
__global__ void __launch_bounds__(256) attnproj_kernel(const float* __restrict__ X,
                                                       int isUser, int N) {
    const float* A  = isUser ? g_A_u : g_A_i;
    const float* be = isUser ? g_beff_u : g_beff_i;
    float* outp     = isUser ? g_aqk_u : g_aqk_i;
    uint32_t* xc    = isUser ? g_xc_u : g_xc_i;

    __shared__ __align__(16) float xs[16][260];
    __shared__ __align__(16) float as[16][260];
    int tid = threadIdx.x;
    int nb = blockIdx.x * 16;

    // stage X tile (16 nodes x 256) + write tf32 copy; float4 coalesced
#pragma unroll
    for (int i = 0; i < 4; i++) {
        int idx = i * 256 + tid;            // 0..1023 over float4s
        int r = idx >> 6, k4 = idx & 63;    // node-row, float4-col
        int gr = nb + r; if (gr >= N) gr = N - 1;
        float4 v = *(const float4*)(X + (size_t)gr * 256 + k4 * 4);
        *(float4*)&xs[r][k4 * 4] = v;
        if (nb + r < N) {
            uint4 c;
            c.x = to_tf32(v.x); c.y = to_tf32(v.y);
            c.z = to_tf32(v.z); c.w = to_tf32(v.w);
            *(uint4*)(xc + (size_t)(nb + r) * 256 + k4 * 4) = c;
        }
    }
    // stage A (16 x 256)
#pragma unroll
    for (int i = 0; i < 4; i++) {
        int idx = i * 256 + tid;
        int r = idx >> 6, k4 = idx & 63;
        *(float4*)&as[r][k4 * 4] = *(const float4*)(A + r * 256 + k4 * 4);
    }
    __syncthreads();

    int n = tid >> 4, j = tid & 15;
    float4 acc = make_float4(0.f, 0.f, 0.f, 0.f);
#pragma unroll 16
    for (int k4 = 0; k4 < 64; k4++) {
        float4 xv = *(const float4*)&xs[n][k4 * 4];
        float4 av = *(const float4*)&as[j][k4 * 4];
        acc.x = fmaf(xv.x, av.x, acc.x);
        acc.y = fmaf(xv.y, av.y, acc.y);
        acc.z = fmaf(xv.z, av.z, acc.z);
        acc.w = fmaf(xv.w, av.w, acc.w);
    }
    if (nb + n < N)
        outp[(size_t)(nb + n) * 16 + j] = (acc.x + acc.y) + (acc.z + acc.w) + be[j];
}

// ---------------- V GEMM: cp.async double-buffered mma.sync tf32 ------------
// C[M,512] = Xc[M,256] @ Wc[512,256]^T + b (operands pre-converted to tf32).
// CTA tile 128(m) x 64(n), K staged 32 at a time, 2-stage cp.async pipeline.
// 8 warps in 4(m) x 2(n); each warp 32x32 via 2x4 m16n8k8 fragments.
__global__ void __launch_bounds__(256) gemm_cp_kernel(const uint32_t* __restrict__ Xc,
                                                      const uint32_t* __restrict__ Wc,
                                                      const float* __restrict__ bias,
                                                      int isUser, int M) {
    float* C = isUser ? g_v_u : g_v_i;
    __shared__ uint32_t As[2][128][36];
    __shared__ uint32_t Bs[2][64][36];
    __shared__ float s_bias[64];

    int tid = threadIdx.x, lane = tid & 31, warp = tid >> 5;
    int wm = (warp & 3) * 32;
    int wn = (warp >> 2) * 32;
    int n0 = blockIdx.x * 64;
    int m0 = blockIdx.y * 128;
    int lq = lane >> 2;
    int lr = lane & 3;

    if (tid < 64) s_bias[tid] = bias[n0 + tid];

    int arow = tid >> 1, acol = (tid & 1) * 16;
    int gr = m0 + arow; if (gr >= M) gr = M - 1;
    const uint32_t* a_src = Xc + (size_t)gr * 256 + acol;
    uint32_t a_dst[2];
    a_dst[0] = (uint32_t)__cvta_generic_to_shared(&As[0][arow][acol]);
    a_dst[1] = (uint32_t)__cvta_generic_to_shared(&As[1][arow][acol]);
    int brow = tid >> 2, bcol = (tid & 3) * 8;
    const uint32_t* b_src = Wc + (size_t)(n0 + brow) * 256 + bcol;
    uint32_t b_dst[2];
    b_dst[0] = (uint32_t)__cvta_generic_to_shared(&Bs[0][brow][bcol]);
    b_dst[1] = (uint32_t)__cvta_generic_to_shared(&Bs[1][brow][bcol]);

    float acc[2][4][4];
#pragma unroll
    for (int mt = 0; mt < 2; mt++)
#pragma unroll
        for (int nt = 0; nt < 4; nt++)
#pragma unroll
            for (int i = 0; i < 4; i++) acc[mt][nt][i] = 0.f;

#define ISSUE(c, buf) do { \
        const uint32_t* _as = a_src + (c) * 32; \
        const uint32_t* _bs = b_src + (c) * 32; \
        cp16(a_dst[buf] + 0,  _as + 0); \
        cp16(a_dst[buf] + 16, _as + 4); \
        cp16(a_dst[buf] + 32, _as + 8); \
        cp16(a_dst[buf] + 48, _as + 12); \
        cp16(b_dst[buf] + 0,  _bs + 0); \
        cp16(b_dst[buf] + 16, _bs + 4); \
        asm volatile("cp.async.commit_group;" ::: "memory"); \
    } while (0)

    ISSUE(0, 0);
    ISSUE(1, 1);

#pragma unroll
    for (int c = 0; c < 8; c++) {
        if (c < 7) asm volatile("cp.async.wait_group 1;" ::: "memory");
        else       asm volatile("cp.async.wait_group 0;" ::: "memory");
        __syncthreads();
        int bf = c & 1;
#pragma unroll
        for (int kk = 0; kk < 4; kk++) {
            int k0 = kk * 8;
            uint32_t b[4][2];
#pragma unroll
            for (int nt = 0; nt < 4; nt++) {
                int n = wn + nt * 8 + lq;
                b[nt][0] = Bs[bf][n][k0 + lr];
                b[nt][1] = Bs[bf][n][k0 + lr + 4];
            }
#pragma unroll
            for (int mt = 0; mt < 2; mt++) {
                int r0 = wm + mt * 16 + lq;
                uint32_t a0 = As[bf][r0][k0 + lr];
                uint32_t a1 = As[bf][r0 + 8][k0 + lr];
                uint32_t a2 = As[bf][r0][k0 + lr + 4];
                uint32_t a3 = As[bf][r0 + 8][k0 + lr + 4];
#pragma unroll
                for (int nt = 0; nt < 4; nt++)
                    mma_tf32(acc[mt][nt], a0, a1, a2, a3, b[nt][0], b[nt][1]);
            }
        }
        __syncthreads();
        if (c + 2 < 8) ISSUE(c + 2, bf);
    }
#undef ISSUE

#pragma unroll
    for (int mt = 0; mt < 2; mt++) {
        int row = m0 + wm + mt * 16 + lq;
#pragma unroll
        for (int nt = 0; nt < 4; nt++) {
            int cl = wn + nt * 8 + 2 * lr;
            float bx = s_bias[cl], by = s_bias[cl + 1];
            if (row < M) {
                float2 o = make_float2(acc[mt][nt][0] + bx, acc[mt][nt][1] + by);
                *(float2*)(C + (size_t)row * 512 + n0 + cl) = o;
            }
            if (row + 8 < M) {
                float2 o = make_float2(acc[mt][nt][2] + bx, acc[mt][nt][3] + by);
                *(float2*)(C + (size_t)(row + 8) * 512 + n0 + cl) = o;
            }
        }
    }
}

// ---------------- edge phase (all 3 etypes per launch; grid.y = etype) ------
// Scores are sums of small projections, so softmax without max-subtraction is
// numerically safe and analytically identical (exp(max) cancels).
__global__ void score_all(EP3 P) {
    int et = blockIdx.y;
    EP p = P.e[et];
    int e = blockIdx.x * blockDim.x + threadIdx.x;
    if (e >= p.E) return;
    int s = p.src[e], d = p.dst[e];
    float* den = g_den + (size_t)et * NU_MAX * 8;
    float* deg = g_deg + (size_t)et * NU_MAX;
    float* edge = g_edge + (size_t)et * E_MAX * 8;
    float4 ak0 = *(const float4*)(p.aqk_s + s * 16 + 8);
    float4 ak1 = *(const float4*)(p.aqk_s + s * 16 + 12);
    float4 aq0 = *(const float4*)(p.aqk_d + d * 16);
    float4 aq1 = *(const float4*)(p.aqk_d + d * 16 + 4);
    float ex[8];
    ex[0] = __expf((ak0.x + aq0.x) * 0.125f);
    ex[1] = __expf((ak0.y + aq0.y) * 0.125f);
    ex[2] = __expf((ak0.z + aq0.z) * 0.125f);
    ex[3] = __expf((ak0.w + aq0.w) * 0.125f);
    ex[4] = __expf((ak1.x + aq1.x) * 0.125f);
    ex[5] = __expf((ak1.y + aq1.y) * 0.125f);
    ex[6] = __expf((ak1.z + aq1.z) * 0.125f);
    ex[7] = __expf((ak1.w + aq1.w) * 0.125f);
    *(float4*)(edge + e * 8)     = make_float4(ex[0], ex[1], ex[2], ex[3]);
    *(float4*)(edge + e * 8 + 4) = make_float4(ex[4], ex[5], ex[6], ex[7]);
#pragma unroll
    for (int h = 0; h < 8; h++) atomicAdd(&den[d * 8 + h], ex[h]);
    atomicAdd(&deg[d], 1.0f);
}

// den[d,h] <- 1 / (den[d,h] * max(deg[d],1))  (per-node normalizer, in place)
__global__ void norm_all(int NUr, int NIr) {
    int et = blockIdx.y;
    int i = blockIdx.x * blockDim.x + threadIdx.x;
    int Nd = (et == 0) ? NIr : NUr;
    if (i >= Nd * 8) return;
    float* den = g_den + (size_t)et * NU_MAX * 8;
    const float* deg = g_deg + (size_t)et * NU_MAX;
    float dc = fmaxf(deg[i >> 3], 1.0f);
    den[i] = 1.0f / (den[i] * dc);
}

// message scatter: one thread per (edge, float4-quad); contiguous 2KB per edge
__global__ void msg_all(EP3 P) {
    int et = blockIdx.y;
    EP p = P.e[et];
    int idx = blockIdx.x * blockDim.x + threadIdx.x;
    if (idx >= p.E * 128) return;
    int e = idx >> 7, q = idx & 127;
    int h = q >> 4;
    const float* edge = g_edge + (size_t)et * E_MAX * 8;
    const float* den = g_den + (size_t)et * NU_MAX * 8;
    int s = p.src[e], d = p.dst[e];
    float a = edge[e * 8 + h] * __ldg(&den[d * 8 + h]);
    float4 vv = *(const float4*)(p.v_s + (size_t)s * 512 + q * 4);
    float x = vv.x * a, y = vv.y * a, z = vv.z * a, w = vv.w * a;
    float* pd = p.outp + (size_t)d * 512 + q * 4;
    asm volatile("red.global.add.v4.f32 [%0], {%1,%2,%3,%4};"
                 :: "l"(pd), "f"(x), "f"(y), "f"(z), "f"(w)
                 : "memory");
}

// ---------------- host ----------------
extern "C" void kernel_launch(void* const* d_in, const int* in_sizes, int n_in,
                              void* d_out, int out_size) {
    const float* x_u  = (const float*)d_in[0];
    const float* x_i  = (const float*)d_in[1];
    const float* Wq_u = (const float*)d_in[2];  const float* bq_u = (const float*)d_in[3];
    const float* Wk_u = (const float*)d_in[4];  const float* bk_u = (const float*)d_in[5];
    const float* Wv_u = (const float*)d_in[6];  const float* bv_u = (const float*)d_in[7];
    const float* Wq_i = (const float*)d_in[8];  const float* bq_i = (const float*)d_in[9];
    const float* Wk_i = (const float*)d_in[10]; const float* bk_i = (const float*)d_in[11];
    const float* Wv_i = (const float*)d_in[12]; const float* bv_i = (const float*)d_in[13];
    const float* wa_u = (const float*)d_in[14]; const float* wa_i = (const float*)d_in[15];
    const int* src_c  = (const int*)d_in[16];   const int* dst_c  = (const int*)d_in[17];
    const int* src_cb = (const int*)d_in[18];   const int* dst_cb = (const int*)d_in[19];
    const int* src_f  = (const int*)d_in[20];   const int* dst_f  = (const int*)d_in[21];

    int NU = in_sizes[0] / 256;
    int NI = in_sizes[1] / 256;
    int E0 = in_sizes[16], E1 = in_sizes[18], E2 = in_sizes[20];
    int Emax = E0 > E1 ? E0 : E1; if (E2 > Emax) Emax = E2;
    int Nmax = NU > NI ? NU : NI;

    float* out_user = (float*)d_out;
    float* out_item = out_user + (size_t)NU * 512;

    void *p_den, *p_deg, *p_vu, *p_vi, *p_aqku, *p_aqki, *p_xcu, *p_xci, *p_wcu, *p_wci;
    cudaGetSymbolAddress(&p_den, g_den);
    cudaGetSymbolAddress(&p_deg, g_deg);
    cudaGetSymbolAddress(&p_vu, g_v_u);
    cudaGetSymbolAddress(&p_vi, g_v_i);
    cudaGetSymbolAddress(&p_aqku, g_aqk_u);
    cudaGetSymbolAddress(&p_aqki, g_aqk_i);
    cudaGetSymbolAddress(&p_xcu, g_xc_u);
    cudaGetSymbolAddress(&p_xci, g_xc_i);
    cudaGetSymbolAddress(&p_wcu, g_wc_u);
    cudaGetSymbolAddress(&p_wci, g_wc_i);

    cudaMemsetAsync(d_out, 0, (size_t)(NU + NI) * 512 * sizeof(float));
    cudaMemsetAsync(p_den, 0, sizeof(float) * 3 * NU_MAX * 8);
    cudaMemsetAsync(p_deg, 0, sizeof(float) * 3 * NU_MAX);

    prep_kernel<<<4, 256>>>(Wq_u, bq_u, Wk_u, bk_u, Wq_i, bq_i, Wk_i, bk_i, wa_u, wa_i);
    wconv_kernel<<<512, 256>>>(Wv_u, Wv_i);
    attnproj_kernel<<<(NU + 15) / 16, 256>>>(x_u, 1, NU);
    attnproj_kernel<<<(NI + 15) / 16, 256>>>(x_i, 0, NI);
    gemm_cp_kernel<<<dim3(8, (NU + 127) / 128), 256>>>(
        (const uint32_t*)p_xcu, (const uint32_t*)p_wcu, bv_u, 1, NU);
    gemm_cp_kernel<<<dim3(8, (NI + 127) / 128), 256>>>(
        (const uint32_t*)p_xci, (const uint32_t*)p_wci, bv_i, 0, NI);

    EP3 P;
    // ('user','clicks','item'): src=user, dst=item -> h_item
    P.e[0] = {src_c, dst_c, (const float*)p_aqku, (const float*)p_aqki,
              (const float*)p_vu, out_item, E0, 0};
    // ('item','clicked_by','user'): src=item, dst=user -> h_user
    P.e[1] = {src_cb, dst_cb, (const float*)p_aqki, (const float*)p_aqku,
              (const float*)p_vi, out_user, E1, 0};
    // ('user','follows','user') -> h_user (accumulates via red.add)
    P.e[2] = {src_f, dst_f, (const float*)p_aqku, (const float*)p_aqku,
              (const float*)p_vu, out_user, E2, 0};

    dim3 gb((Emax + 255) / 256, 3);
    score_all<<<gb, 256>>>(P);
    norm_all<<<dim3((Nmax * 8 + 255) / 256, 3), 256>>>(NU, NI);
    msg_all<<<dim3((Emax * 128 + 255) / 256, 3), 256>>>(P);
}

// round 14
// speedup vs baseline: 1.5205x; 1.0060x over previous
#include <cuda_runtime.h>
#include <cstdint>

#define NU_MAX 50000
#define NI_MAX 50000
#define E_MAX  100000

// ---------------- device scratch (static; no allocations allowed) ----------
__device__ float g_v_u[NU_MAX * 512];     // V projection, user
__device__ float g_v_i[NI_MAX * 512];     // V projection, item
__device__ float g_aqk_u[NU_MAX * 16];    // per node: [0..7]=aq, [8..15]=ak
__device__ float g_aqk_i[NI_MAX * 16];
__device__ uint32_t g_xc_u[NU_MAX * 256]; // tf32(RNA)-converted X, user
__device__ uint32_t g_xc_i[NI_MAX * 256]; // tf32(RNA)-converted X, item
__device__ uint32_t g_wc_u[512 * 256];    // tf32(RNA)-converted Wv_user
__device__ uint32_t g_wc_i[512 * 256];    // tf32(RNA)-converted Wv_item
__device__ float g_A_u[16 * 256];         // effective attn proj: rows 0..7 q, 8..15 k
__device__ float g_A_i[16 * 256];
__device__ float g_beff_u[16];
__device__ float g_beff_i[16];
__device__ float g_den[3 * NU_MAX * 8];   // sum(exp) -> 1/(sum*deg) after norm_all
__device__ int   g_cnt[3 * NU_MAX];       // edges per (etype,dst)
__device__ int   g_off[3 * NU_MAX];       // CSR exclusive offsets
__device__ int   g_fill[3 * NU_MAX];      // fill cursors
__device__ int   g_csr[3 * E_MAX];        // edge ids grouped by dst
__device__ float g_edge[3 * E_MAX * 8];   // exp(score)

struct EP {
    const int* src; const int* dst;
    const float* aqk_s; const float* aqk_d;
    const float* v_s; float* outp;
    int E; int pad;
};
struct EP3 { EP e[3]; };

// ---------------- helpers ----------------
__device__ __forceinline__ uint32_t to_tf32(float f) {
    uint32_t r;
    asm("cvt.rna.tf32.f32 %0, %1;" : "=r"(r) : "f"(f));
    return r;
}
__device__ __forceinline__ void mma_tf32(float* c, uint32_t a0, uint32_t a1,
                                         uint32_t a2, uint32_t a3,
                                         uint32_t b0, uint32_t b1) {
    asm("mma.sync.aligned.m16n8k8.row.col.f32.tf32.tf32.f32 "
        "{%0,%1,%2,%3}, {%4,%5,%6,%7}, {%8,%9}, {%0,%1,%2,%3};"
        : "+f"(c[0]), "+f"(c[1]), "+f"(c[2]), "+f"(c[3])
        : "r"(a0), "r"(a1), "r"(a2), "r"(a3), "r"(b0), "r"(b1));
}
__device__ __forceinline__ void cp16(uint32_t smem_dst, const void* gsrc) {
    asm volatile("cp.async.cg.shared.global [%0], [%1], 16;"
                 :: "r"(smem_dst), "l"(gsrc) : "memory");
}

// ---------------- prep: fold wa into Wq/Wk -> effective [16,256] matrices ---
__global__ void prep_kernel(const float* __restrict__ Wq_u, const float* __restrict__ bq_u,
                            const float* __restrict__ Wk_u, const float* __restrict__ bk_u,
                            const float* __restrict__ Wq_i, const float* __restrict__ bq_i,
                            const float* __restrict__ Wk_i, const float* __restrict__ bk_i,
                            const float* __restrict__ wa_u, const float* __restrict__ wa_i) {
    int b = blockIdx.x;  // 0:Wq_u 1:Wk_u 2:Wq_i 3:Wk_i
    const float* W    = (b == 0) ? Wq_u : (b == 1) ? Wk_u : (b == 2) ? Wq_i : Wk_i;
    const float* bias = (b == 0) ? bq_u : (b == 1) ? bk_u : (b == 2) ? bq_i : bk_i;
    const float* wa   = (b < 2) ? wa_u : wa_i;
    float* A  = (b < 2) ? g_A_u : g_A_i;
    float* be = (b < 2) ? g_beff_u : g_beff_i;
    int rowoff = (b & 1) * 8;
    int k = threadIdx.x;
    __shared__ float was[64];
    if (k < 64) was[k] = wa[k];
    __syncthreads();
#pragma unroll
    for (int h = 0; h < 8; h++) {
        float s = 0.f;
        for (int d = 0; d < 64; d++) s += W[(h * 64 + d) * 256 + k] * was[d];
        A[(rowoff + h) * 256 + k] = s;
    }
    if (k < 8) {
        float s = 0.f;
        for (int d = 0; d < 64; d++) s += bias[k * 64 + d] * was[d];
        be[rowoff + k] = s;
    }
}

// ---------------- Wv -> tf32 conversion (RNA, same numerics as before) ------
__global__ void wconv_kernel(const float* __restrict__ Wv_u,
                             const float* __restrict__ Wv_i) {
    int i = blockIdx.x * blockDim.x + threadIdx.x;  // 512*256 total
    g_wc_u[i] = to_tf32(Wv_u[i]);
    g_wc_i[i] = to_tf32(Wv_i[i]);
}

// ---------------- attn projections + X -> tf32 copy -------------------------
__global__ void __launch_bounds__(256) attnproj_kernel(const float* __restrict__ X,
                                                       int isUser, int N) {
    const float* A  = isUser ? g_A_u : g_A_i;
    const float* be = isUser ? g_beff_u : g_beff_i;
    float* outp     = isUser ? g_aqk_u : g_aqk_i;
    uint32_t* xc    = isUser ? g_xc_u : g_xc_i;

    __shared__ __align__(16) float xs[16][260];
    __shared__ __align__(16) float as[16][260];
    int tid = threadIdx.x;
    int nb = blockIdx.x * 16;

#pragma unroll
    for (int i = 0; i < 4; i++) {
        int idx = i * 256 + tid;
        int r = idx >> 6, k4 = idx & 63;
        int gr = nb + r; if (gr >= N) gr = N - 1;
        float4 v = *(const float4*)(X + (size_t)gr * 256 + k4 * 4);
        *(float4*)&xs[r][k4 * 4] = v;
        if (nb + r < N) {
            uint4 c;
            c.x = to_tf32(v.x); c.y = to_tf32(v.y);
            c.z = to_tf32(v.z); c.w = to_tf32(v.w);
            *(uint4*)(xc + (size_t)(nb + r) * 256 + k4 * 4) = c;
        }
    }
#pragma unroll
    for (int i = 0; i < 4; i++) {
        int idx = i * 256 + tid;
        int r = idx >> 6, k4 = idx & 63;
        *(float4*)&as[r][k4 * 4] = *(const float4*)(A + r * 256 + k4 * 4);
    }
    __syncthreads();

    int n = tid >> 4, j = tid & 15;
    float4 acc = make_float4(0.f, 0.f, 0.f, 0.f);
#pragma unroll 16
    for (int k4 = 0; k4 < 64; k4++) {
        float4 xv = *(const float4*)&xs[n][k4 * 4];
        float4 av = *(const float4*)&as[j][k4 * 4];
        acc.x = fmaf(xv.x, av.x, acc.x);
        acc.y = fmaf(xv.y, av.y, acc.y);
        acc.z = fmaf(xv.z, av.z, acc.z);
        acc.w = fmaf(xv.w, av.w, acc.w);
    }
    if (nb + n < N)
        outp[(size_t)(nb + n) * 16 + j] = (acc.x + acc.y) + (acc.z + acc.w) + be[j];
}

// ---------------- V GEMM: cp.async double-buffered mma.sync tf32 ------------
__global__ void __launch_bounds__(256) gemm_cp_kernel(const uint32_t* __restrict__ Xc,
                                                      const uint32_t* __restrict__ Wc,
                                                      const float* __restrict__ bias,
                                                      int isUser, int M) {
    float* C = isUser ? g_v_u : g_v_i;
    __shared__ uint32_t As[2][128][36];
    __shared__ uint32_t Bs[2][64][36];
    __shared__ float s_bias[64];

    int tid = threadIdx.x, lane = tid & 31, warp = tid >> 5;
    int wm = (warp & 3) * 32;
    int wn = (warp >> 2) * 32;
    int n0 = blockIdx.x * 64;
    int m0 = blockIdx.y * 128;
    int lq = lane >> 2;
    int lr = lane & 3;

    if (tid < 64) s_bias[tid] = bias[n0 + tid];

    int arow = tid >> 1, acol = (tid & 1) * 16;
    int gr = m0 + arow; if (gr >= M) gr = M - 1;
    const uint32_t* a_src = Xc + (size_t)gr * 256 + acol;
    uint32_t a_dst[2];
    a_dst[0] = (uint32_t)__cvta_generic_to_shared(&As[0][arow][acol]);
    a_dst[1] = (uint32_t)__cvta_generic_to_shared(&As[1][arow][acol]);
    int brow = tid >> 2, bcol = (tid & 3) * 8;
    const uint32_t* b_src = Wc + (size_t)(n0 + brow) * 256 + bcol;
    uint32_t b_dst[2];
    b_dst[0] = (uint32_t)__cvta_generic_to_shared(&Bs[0][brow][bcol]);
    b_dst[1] = (uint32_t)__cvta_generic_to_shared(&Bs[1][brow][bcol]);

    float acc[2][4][4];
#pragma unroll
    for (int mt = 0; mt < 2; mt++)
#pragma unroll
        for (int nt = 0; nt < 4; nt++)
#pragma unroll
            for (int i = 0; i < 4; i++) acc[mt][nt][i] = 0.f;

#define ISSUE(c, buf) do { \
        const uint32_t* _as = a_src + (c) * 32; \
        const uint32_t* _bs = b_src + (c) * 32; \
        cp16(a_dst[buf] + 0,  _as + 0); \
        cp16(a_dst[buf] + 16, _as + 4); \
        cp16(a_dst[buf] + 32, _as + 8); \
        cp16(a_dst[buf] + 48, _as + 12); \
        cp16(b_dst[buf] + 0,  _bs + 0); \
        cp16(b_dst[buf] + 16, _bs + 4); \
        asm volatile("cp.async.commit_group;" ::: "memory"); \
    } while (0)

    ISSUE(0, 0);
    ISSUE(1, 1);

#pragma unroll
    for (int c = 0; c < 8; c++) {
        if (c < 7) asm volatile("cp.async.wait_group 1;" ::: "memory");
        else       asm volatile("cp.async.wait_group 0;" ::: "memory");
        __syncthreads();
        int bf = c & 1;
#pragma unroll
        for (int kk = 0; kk < 4; kk++) {
            int k0 = kk * 8;
            uint32_t b[4][2];
#pragma unroll
            for (int nt = 0; nt < 4; nt++) {
                int n = wn + nt * 8 + lq;
                b[nt][0] = Bs[bf][n][k0 + lr];
                b[nt][1] = Bs[bf][n][k0 + lr + 4];
            }
#pragma unroll
            for (int mt = 0; mt < 2; mt++) {
                int r0 = wm + mt * 16 + lq;
                uint32_t a0 = As[bf][r0][k0 + lr];
                uint32_t a1 = As[bf][r0 + 8][k0 + lr];
                uint32_t a2 = As[bf][r0][k0 + lr + 4];
                uint32_t a3 = As[bf][r0 + 8][k0 + lr + 4];
#pragma unroll
                for (int nt = 0; nt < 4; nt++)
                    mma_tf32(acc[mt][nt], a0, a1, a2, a3, b[nt][0], b[nt][1]);
            }
        }
        __syncthreads();
        if (c + 2 < 8) ISSUE(c + 2, bf);
    }
#undef ISSUE

#pragma unroll
    for (int mt = 0; mt < 2; mt++) {
        int row = m0 + wm + mt * 16 + lq;
#pragma unroll
        for (int nt = 0; nt < 4; nt++) {
            int cl = wn + nt * 8 + 2 * lr;
            float bx = s_bias[cl], by = s_bias[cl + 1];
            if (row < M) {
                float2 o = make_float2(acc[mt][nt][0] + bx, acc[mt][nt][1] + by);
                *(float2*)(C + (size_t)row * 512 + n0 + cl) = o;
            }
            if (row + 8 < M) {
                float2 o = make_float2(acc[mt][nt][2] + bx, acc[mt][nt][3] + by);
                *(float2*)(C + (size_t)(row + 8) * 512 + n0 + cl) = o;
            }
        }
    }
}

// ---------------- edge phase ------------------------------------------------
// Scores are sums of small projections, so softmax without max-subtraction is
// numerically safe and analytically identical (exp(max) cancels).
__global__ void score_all(EP3 P) {
    int et = blockIdx.y;
    EP p = P.e[et];
    int e = blockIdx.x * blockDim.x + threadIdx.x;
    if (e >= p.E) return;
    int s = p.src[e], d = p.dst[e];
    float* den = g_den + (size_t)et * NU_MAX * 8;
    int* cnt = g_cnt + (size_t)et * NU_MAX;
    float* edge = g_edge + (size_t)et * E_MAX * 8;
    float4 ak0 = *(const float4*)(p.aqk_s + s * 16 + 8);
    float4 ak1 = *(const float4*)(p.aqk_s + s * 16 + 12);
    float4 aq0 = *(const float4*)(p.aqk_d + d * 16);
    float4 aq1 = *(const float4*)(p.aqk_d + d * 16 + 4);
    float ex[8];
    ex[0] = __expf((ak0.x + aq0.x) * 0.125f);
    ex[1] = __expf((ak0.y + aq0.y) * 0.125f);
    ex[2] = __expf((ak0.z + aq0.z) * 0.125f);
    ex[3] = __expf((ak0.w + aq0.w) * 0.125f);
    ex[4] = __expf((ak1.x + aq1.x) * 0.125f);
    ex[5] = __expf((ak1.y + aq1.y) * 0.125f);
    ex[6] = __expf((ak1.z + aq1.z) * 0.125f);
    ex[7] = __expf((ak1.w + aq1.w) * 0.125f);
    *(float4*)(edge + e * 8)     = make_float4(ex[0], ex[1], ex[2], ex[3]);
    *(float4*)(edge + e * 8 + 4) = make_float4(ex[4], ex[5], ex[6], ex[7]);
#pragma unroll
    for (int h = 0; h < 8; h++) atomicAdd(&den[d * 8 + h], ex[h]);
    atomicAdd(&cnt[d], 1);
}

// exclusive scan of g_cnt per etype -> g_off. One 1024-thread block per etype.
__global__ void __launch_bounds__(1024) scan_all(int NUr, int NIr) {
    int et = blockIdx.x;
    int Nd = (et == 0) ? NIr : NUr;
    const int* cnt = g_cnt + (size_t)et * NU_MAX;
    int* off = g_off + (size_t)et * NU_MAX;
    int tid = threadIdx.x;
    int chunk = (Nd + 1023) >> 10;
    int s0 = tid * chunk, s1 = s0 + chunk;
    if (s1 > Nd) s1 = Nd;
    int s = 0;
    for (int i = s0; i < s1; i++) s += cnt[i];
    __shared__ int sh[1024];
    sh[tid] = s;
    __syncthreads();
    for (int o = 1; o < 1024; o <<= 1) {
        int add = (tid >= o) ? sh[tid - o] : 0;
        __syncthreads();
        sh[tid] += add;
        __syncthreads();
    }
    int run = sh[tid] - s;  // exclusive prefix of this chunk
    for (int i = s0; i < s1; i++) { off[i] = run; run += cnt[i]; }
}

// scatter edge ids into CSR slots
__global__ void fill_all(EP3 P) {
    int et = blockIdx.y;
    EP p = P.e[et];
    int e = blockIdx.x * blockDim.x + threadIdx.x;
    if (e >= p.E) return;
    int d = p.dst[e];
    int pos = g_off[(size_t)et * NU_MAX + d] +
              atomicAdd(&g_fill[(size_t)et * NU_MAX + d], 1);
    g_csr[(size_t)et * E_MAX + pos] = e;
}

// den[d,h] <- 1 / (den[d,h] * max(cnt[d],1))
__global__ void norm_all(int NUr, int NIr) {
    int et = blockIdx.y;
    int i = blockIdx.x * blockDim.x + threadIdx.x;
    int Nd = (et == 0) ? NIr : NUr;
    if (i >= Nd * 8) return;
    float* den = g_den + (size_t)et * NU_MAX * 8;
    float dc = (float)max(g_cnt[(size_t)et * NU_MAX + (i >> 3)], 1);
    den[i] = 1.0f / (den[i] * dc);
}

// ---------------- gather: one block per dst node, plain stores, no atomics --
// item: etype0 (src=user, v_u)
__global__ void __launch_bounds__(128) gather_item(const int* __restrict__ src0,
                                                   float* __restrict__ outp, int NIr) {
    int d = blockIdx.x;
    int t = threadIdx.x, h = t >> 4;
    float w = g_den[d * 8 + h];
    int base = g_off[d], n = g_cnt[d];
    float4 acc = make_float4(0.f, 0.f, 0.f, 0.f);
    for (int i = 0; i < n; i++) {
        int e = g_csr[base + i];
        float a = g_edge[(size_t)e * 8 + h] * w;
        int s = src0[e];
        float4 v = *(const float4*)(g_v_u + (size_t)s * 512 + t * 4);
        acc.x = fmaf(v.x, a, acc.x); acc.y = fmaf(v.y, a, acc.y);
        acc.z = fmaf(v.z, a, acc.z); acc.w = fmaf(v.w, a, acc.w);
    }
    *(float4*)(outp + (size_t)d * 512 + t * 4) = acc;
}

// user: etype1 (src=item, v_i) + etype2 (src=user, v_u), summed
__global__ void __launch_bounds__(128) gather_user(const int* __restrict__ src1,
                                                   const int* __restrict__ src2,
                                                   float* __restrict__ outp, int NUr) {
    int d = blockIdx.x;
    int t = threadIdx.x, h = t >> 4;
    float4 acc = make_float4(0.f, 0.f, 0.f, 0.f);
    {
        float w = g_den[(size_t)NU_MAX * 8 + d * 8 + h];
        int base = g_off[NU_MAX + d], n = g_cnt[NU_MAX + d];
        for (int i = 0; i < n; i++) {
            int e = g_csr[E_MAX + base + i];
            float a = g_edge[(size_t)E_MAX * 8 + e * 8 + h] * w;
            int s = src1[e];
            float4 v = *(const float4*)(g_v_i + (size_t)s * 512 + t * 4);
            acc.x = fmaf(v.x, a, acc.x); acc.y = fmaf(v.y, a, acc.y);
            acc.z = fmaf(v.z, a, acc.z); acc.w = fmaf(v.w, a, acc.w);
        }
    }
    {
        float w = g_den[(size_t)2 * NU_MAX * 8 + d * 8 + h];
        int base = g_off[2 * NU_MAX + d], n = g_cnt[2 * NU_MAX + d];
        for (int i = 0; i < n; i++) {
            int e = g_csr[2 * E_MAX + base + i];
            float a = g_edge[(size_t)2 * E_MAX * 8 + e * 8 + h] * w;
            int s = src2[e];
            float4 v = *(const float4*)(g_v_u + (size_t)s * 512 + t * 4);
            acc.x = fmaf(v.x, a, acc.x); acc.y = fmaf(v.y, a, acc.y);
            acc.z = fmaf(v.z, a, acc.z); acc.w = fmaf(v.w, a, acc.w);
        }
    }
    *(float4*)(outp + (size_t)d * 512 + t * 4) = acc;
}

// ---------------- host ----------------
extern "C" void kernel_launch(void* const* d_in, const int* in_sizes, int n_in,
                              void* d_out, int out_size) {
    const float* x_u  = (const float*)d_in[0];
    const float* x_i  = (const float*)d_in[1];
    const float* Wq_u = (const float*)d_in[2];  const float* bq_u = (const float*)d_in[3];
    const float* Wk_u = (const float*)d_in[4];  const float* bk_u = (const float*)d_in[5];
    const float* Wv_u = (const float*)d_in[6];  const float* bv_u = (const float*)d_in[7];
    const float* Wq_i = (const float*)d_in[8];  const float* bq_i = (const float*)d_in[9];
    const float* Wk_i = (const float*)d_in[10]; const float* bk_i = (const float*)d_in[11];
    const float* Wv_i = (const float*)d_in[12]; const float* bv_i = (const float*)d_in[13];
    const float* wa_u = (const float*)d_in[14]; const float* wa_i = (const float*)d_in[15];
    const int* src_c  = (const int*)d_in[16];   const int* dst_c  = (const int*)d_in[17];
    const int* src_cb = (const int*)d_in[18];   const int* dst_cb = (const int*)d_in[19];
    const int* src_f  = (const int*)d_in[20];   const int* dst_f  = (const int*)d_in[21];

    int NU = in_sizes[0] / 256;
    int NI = in_sizes[1] / 256;
    int E0 = in_sizes[16], E1 = in_sizes[18], E2 = in_sizes[20];
    int Emax = E0 > E1 ? E0 : E1; if (E2 > Emax) Emax = E2;
    int Nmax = NU > NI ? NU : NI;

    float* out_user = (float*)d_out;
    float* out_item = out_user + (size_t)NU * 512;

    void *p_den, *p_cnt, *p_fill, *p_vu, *p_vi, *p_aqku, *p_aqki, *p_xcu, *p_xci,
         *p_wcu, *p_wci;
    cudaGetSymbolAddress(&p_den, g_den);
    cudaGetSymbolAddress(&p_cnt, g_cnt);
    cudaGetSymbolAddress(&p_fill, g_fill);
    cudaGetSymbolAddress(&p_vu, g_v_u);
    cudaGetSymbolAddress(&p_vi, g_v_i);
    cudaGetSymbolAddress(&p_aqku, g_aqk_u);
    cudaGetSymbolAddress(&p_aqki, g_aqk_i);
    cudaGetSymbolAddress(&p_xcu, g_xc_u);
    cudaGetSymbolAddress(&p_xci, g_xc_i);
    cudaGetSymbolAddress(&p_wcu, g_wc_u);
    cudaGetSymbolAddress(&p_wci, g_wc_i);

    cudaMemsetAsync(p_den, 0, sizeof(float) * 3 * NU_MAX * 8);
    cudaMemsetAsync(p_cnt, 0, sizeof(int) * 3 * NU_MAX);
    cudaMemsetAsync(p_fill, 0, sizeof(int) * 3 * NU_MAX);

    prep_kernel<<<4, 256>>>(Wq_u, bq_u, Wk_u, bk_u, Wq_i, bq_i, Wk_i, bk_i, wa_u, wa_i);
    wconv_kernel<<<512, 256>>>(Wv_u, Wv_i);
    attnproj_kernel<<<(NU + 15) / 16, 256>>>(x_u, 1, NU);
    attnproj_kernel<<<(NI + 15) / 16, 256>>>(x_i, 0, NI);
    gemm_cp_kernel<<<dim3(8, (NU + 127) / 128), 256>>>(
        (const uint32_t*)p_xcu, (const uint32_t*)p_wcu, bv_u, 1, NU);
    gemm_cp_kernel<<<dim3(8, (NI + 127) / 128), 256>>>(
        (const uint32_t*)p_xci, (const uint32_t*)p_wci, bv_i, 0, NI);

    EP3 P;
    // ('user','clicks','item'): src=user, dst=item -> h_item
    P.e[0] = {src_c, dst_c, (const float*)p_aqku, (const float*)p_aqki,
              (const float*)p_vu, out_item, E0, 0};
    // ('item','clicked_by','user'): src=item, dst=user -> h_user
    P.e[1] = {src_cb, dst_cb, (const float*)p_aqki, (const float*)p_aqku,
              (const float*)p_vi, out_user, E1, 0};
    // ('user','follows','user') -> h_user
    P.e[2] = {src_f, dst_f, (const float*)p_aqku, (const float*)p_aqku,
              (const float*)p_vu, out_user, E2, 0};

    dim3 gb((Emax + 255) / 256, 3);
    score_all<<<gb, 256>>>(P);
    scan_all<<<3, 1024>>>(NU, NI);
    fill_all<<<gb, 256>>>(P);
    norm_all<<<dim3((Nmax * 8 + 255) / 256, 3), 256>>>(NU, NI);
    gather_item<<<NI, 128>>>(src_c, out_item, NI);
    gather_user<<<NU, 128>>>(src_cb, src_f, out_user, NU);
}